// round 14
// baseline (speedup 1.0000x reference)
#include <cuda_runtime.h>
#include <cuda_fp16.h>
#include <math.h>
#include <stdint.h>

// ============================================================================
// conv1_max_embedding: feats[N,256] @ Wc[256,512] -> segment_max over batch_idx
//   -> fc1 [512,1024] -> BN(train) -> relu -> fc2 [1024,256] -> out [64,256]
//
// Strategy R14 (= R13 resubmitted after infra failure; audited, no defects):
//   - BK 32->64: half the wait+barrier events (4 per block instead of 8)
//   - hoisted ldsm address bases (swizzle term is loop-invariant: krow&7==lane&7)
//   - same BM=128 x BN=128, 256 thr, 2 CTAs/SM, fp16 mma, ARGMAX epilogue,
//     exact fp32 recompute; mma order unchanged -> bitwise-identical result
// ============================================================================

#define NB 64
#define C_IN 256
#define C_CONV 512
#define D1 1024
#define D2 256
#define BM 128
#define BN 128
#define BK 64            // k per smem stage (4 mma k-steps)
#define NKT (C_IN / BK)  // 4
#define NSTAGE 3
#define MAXN 500032
#define MAXBLK (MAXN / 256 + 1)
#define MAXTILES 4160

#define A_STRIDE 144     // bytes per A smem row (64 halves=128B, padded to 144)
#define B_STRIDE 256     // bytes per B smem row (128 halves)
#define A_STAGE (BM * A_STRIDE)        // 18432
#define B_STAGE (BK * B_STRIDE)        // 16384
#define B_REGION (NSTAGE * A_STAGE)    // 55296
#define SMEM_DYN (NSTAGE * (A_STAGE + B_STAGE))   // 104448

__device__ int   g_part[MAXBLK * NB];
__device__ int   g_cursor[NB];
__device__ int   g_ntiles;
__device__ int   g_tile_seg[MAXTILES];
__device__ int   g_tile_row[MAXTILES];
__device__ int   g_tile_nrows[MAXTILES];
__device__ int   g_perm[MAXN];
__device__ unsigned long long g_argkey[NB * C_CONV];
__device__ float g_pooled[NB * C_CONV];
__device__ float g_h[NB * D1];
__device__ float g_hn[NB * D1];
__device__ __half g_afp16[(size_t)MAXN * C_IN];   // 256 MB scratch (sorted rows)
__device__ __half g_wfp16[C_IN * C_CONV];

// ---------------------------------------------------------------------------
// helpers
// ---------------------------------------------------------------------------
__device__ __forceinline__ unsigned long long packkey(float v, int row) {
    unsigned u = __float_as_uint(v);
    u = (u & 0x80000000u) ? ~u : (u | 0x80000000u);  // order-preserving map
    return ((unsigned long long)u << 32) | (unsigned)row;
}

__device__ __forceinline__ void cpa16(uint32_t dst, const void* src) {
    asm volatile("cp.async.cg.shared.global [%0], [%1], 16;"
                 :: "r"(dst), "l"(src) : "memory");
}
__device__ __forceinline__ void cpa_commit() {
    asm volatile("cp.async.commit_group;" ::: "memory");
}
template <int N>
__device__ __forceinline__ void cpa_wait() {
    asm volatile("cp.async.wait_group %0;" :: "n"(N) : "memory");
}

__device__ __forceinline__ void ldmA(uint32_t* r, uint32_t addr) {
    asm volatile("ldmatrix.sync.aligned.m8n8.x4.shared.b16 {%0,%1,%2,%3}, [%4];"
                 : "=r"(r[0]), "=r"(r[1]), "=r"(r[2]), "=r"(r[3]) : "r"(addr));
}
__device__ __forceinline__ void ldmBT(uint32_t* r, uint32_t addr) {
    asm volatile("ldmatrix.sync.aligned.m8n8.x2.trans.shared.b16 {%0,%1}, [%2];"
                 : "=r"(r[0]), "=r"(r[1]) : "r"(addr));
}
__device__ __forceinline__ void mma_f16(float* c, const uint32_t* a,
                                        const uint32_t* b) {
    asm volatile(
        "mma.sync.aligned.m16n8k16.row.col.f32.f16.f16.f32 "
        "{%0,%1,%2,%3}, {%4,%5,%6,%7}, {%8,%9}, {%0,%1,%2,%3};\n"
        : "+f"(c[0]), "+f"(c[1]), "+f"(c[2]), "+f"(c[3])
        : "r"(a[0]), "r"(a[1]), "r"(a[2]), "r"(a[3]), "r"(b[0]), "r"(b[1]));
}

__device__ __forceinline__ uint32_t pack2h(float lo, float hi) {
    __half2 h = __floats2half2_rn(lo, hi);
    return *(uint32_t*)&h;
}

// ---------------------------------------------------------------------------
// 1. partial histogram (no pre-zeroed counters) + argkey zeroing
// ---------------------------------------------------------------------------
__global__ void k_histz(const int* __restrict__ bidx, int N) {
    __shared__ int lc[NB];
    int t = threadIdx.x;
    if (t < NB) lc[t] = 0;
    for (int j = blockIdx.x * 256 + t; j < NB * C_CONV; j += gridDim.x * 256)
        g_argkey[j] = 0ull;
    __syncthreads();
    int i = blockIdx.x * 256 + t;
    if (i < N) atomicAdd(&lc[bidx[i]], 1);
    __syncthreads();
    if (t < NB) g_part[blockIdx.x * NB + t] = lc[t];
}

// ---------------------------------------------------------------------------
// 2. sum partials + prefix scan + tile table (single block, 256 threads)
// ---------------------------------------------------------------------------
__global__ void k_scan(int nblk) {
    __shared__ int part4[4][NB];
    __shared__ int cnt[NB], sbase[NB], stb[NB];
    int t = threadIdx.x;            // 256
    int seg = t & 63, q = t >> 6;
    int s = 0;
    for (int b = q; b < nblk; b += 4) s += g_part[b * NB + seg];
    part4[q][seg] = s;
    __syncthreads();
    if (t < NB)
        cnt[t] = part4[0][t] + part4[1][t] + part4[2][t] + part4[3][t];
    __syncthreads();
    if (t == 0) {
        int acc = 0, ta = 0;
        for (int g = 0; g < NB; g++) {
            sbase[g] = acc; acc += cnt[g];
            stb[g] = ta;    ta += (cnt[g] + BM - 1) >> 7;
        }
        g_ntiles = ta;
    }
    __syncthreads();
    if (t < NB) {
        g_cursor[t] = sbase[t];
        int nt = (cnt[t] + BM - 1) >> 7;
        for (int i = 0; i < nt; i++) {
            int id = stb[t] + i;
            g_tile_seg[id]   = t;
            g_tile_row[id]   = sbase[t] + i * BM;
            g_tile_nrows[id] = min(BM, cnt[t] - i * BM);
        }
    }
}

// ---------------------------------------------------------------------------
// 3. scatter + gather-convert feats to sorted fp16 + convert Wc
// ---------------------------------------------------------------------------
__global__ void k_scatcv(const int* __restrict__ bidx,
                         const float* __restrict__ feats,
                         const float* __restrict__ Wc, int N) {
    __shared__ int lc[NB], lbase[NB];
    __shared__ int sdst[256];
    int t = threadIdx.x;
    if (t < NB) lc[t] = 0;
    __syncthreads();
    int i = blockIdx.x * 256 + t;
    int b = 0, rank = 0;
    if (i < N) {
        b = bidx[i];
        rank = atomicAdd(&lc[b], 1);
    }
    __syncthreads();
    if (t < NB && lc[t] > 0) lbase[t] = atomicAdd(&g_cursor[t], lc[t]);
    __syncthreads();
    int dst = 0;
    if (i < N) {
        dst = lbase[b] + rank;
        g_perm[dst] = i;
    }
    sdst[t] = dst;
    __syncthreads();
    int lane = t & 31, w = t >> 5;
    for (int p = w; p < 256; p += 8) {
        int src = blockIdx.x * 256 + p;
        if (src >= N) break;
        int d = sdst[p];
        const float4* sp = (const float4*)(feats + (size_t)src * C_IN + lane * 8);
        float4 x = sp[0], y = sp[1];
        uint4 o = make_uint4(pack2h(x.x, x.y), pack2h(x.z, x.w),
                             pack2h(y.x, y.y), pack2h(y.z, y.w));
        *(uint4*)(g_afp16 + (size_t)d * C_IN + lane * 8) = o;
    }
    if (blockIdx.x < 64) {
        int j = (blockIdx.x * 256 + t) * 8;
        const float4* sp = (const float4*)(Wc + j);
        float4 x = sp[0], y = sp[1];
        uint4 o = make_uint4(pack2h(x.x, x.y), pack2h(x.z, x.w),
                             pack2h(y.x, y.y), pack2h(y.z, y.w));
        *(uint4*)(g_wfp16 + j) = o;
    }
}

// ---------------------------------------------------------------------------
// 4. FP16 tensor GEMM, BM=128 x BN=128, 256 threads, BK=64, 3-stage cp.async,
//    one barrier per k-tile (4 total), 2 CTAs/SM. ARGMAX epilogue.
//    8 warps (2m x 4n); warp tile 64x32 (mt<4, nt<4)
// ---------------------------------------------------------------------------
__global__ void __launch_bounds__(256, 2)
k_gemm() {
    int tile = blockIdx.y;
    if (tile >= g_ntiles) return;
    int seg      = g_tile_seg[tile];
    int rowstart = g_tile_row[tile];
    int nrows    = g_tile_nrows[tile];
    int n0       = blockIdx.x * BN;

    extern __shared__ __align__(128) char dsm[];

    int tid  = threadIdx.x;
    int lane = tid & 31, wid = tid >> 5;
    int wm = wid & 1, wn = wid >> 1;   // 2 x 4 warp grid

    uint32_t sbase = (uint32_t)__cvta_generic_to_shared(dsm);

    // ---- A copy mapping: 2 threads per row, 64B (4x16B) each
    int ar  = tid >> 1;                 // 0..127
    int akh = tid & 1;                  // 64B half of the 128B row
    const __half* aptr =
        g_afp16 + (size_t)(rowstart + min(ar, nrows - 1)) * C_IN + akh * 32;
    uint32_t adst = sbase + ar * A_STRIDE + akh * 64;
    // ---- B copy mapping: 4 threads per k-row, 64B (4 chunks of 16B) each
    int bk  = tid >> 2;                 // 0..63 k row within stage
    int bq  = tid & 3;                  // which 4-chunk quarter
    const __half* bptr = g_wfp16 + (size_t)bk * C_CONV + n0 + bq * 32;
    int bsw = bk & 7;
    uint32_t bdst = sbase + B_REGION + bk * B_STRIDE;
    int bc0 = ((bq * 4 + 0) ^ bsw) * 16;
    int bc1 = ((bq * 4 + 1) ^ bsw) * 16;
    int bc2 = ((bq * 4 + 2) ^ bsw) * 16;
    int bc3 = ((bq * 4 + 3) ^ bsw) * 16;

    float acc[4][4][4];
#pragma unroll
    for (int mt = 0; mt < 4; mt++)
#pragma unroll
        for (int nt = 0; nt < 4; nt++)
#pragma unroll
            for (int r = 0; r < 4; r++) acc[mt][nt][r] = 0.0f;

    // ---- prologue: issue stages 0 and 1
#pragma unroll
    for (int s = 0; s < NSTAGE - 1; s++) {
        const __half* an = aptr + s * BK;
        cpa16(adst + s * A_STAGE,      an);
        cpa16(adst + s * A_STAGE + 16, an + 8);
        cpa16(adst + s * A_STAGE + 32, an + 16);
        cpa16(adst + s * A_STAGE + 48, an + 24);
        const __half* bn = bptr + (size_t)s * BK * C_CONV;
        cpa16(bdst + s * B_STAGE + bc0, bn);
        cpa16(bdst + s * B_STAGE + bc1, bn + 8);
        cpa16(bdst + s * B_STAGE + bc2, bn + 16);
        cpa16(bdst + s * B_STAGE + bc3, bn + 24);
        cpa_commit();
    }

    // ---- hoisted ldsm address bases (loop-invariant; swizzle uses lane&7)
    int asub = lane >> 3, al7 = lane & 7;
    int arow_frag = (asub & 1) * 8 + al7;
    int akoff = (asub >> 1) * 16;
    int bl15 = lane & 15;
    int aOff[4], bOff[4];
#pragma unroll
    for (int mt = 0; mt < 4; mt++)
        aOff[mt] = (wm * 64 + mt * 16 + arow_frag) * A_STRIDE + akoff;
#pragma unroll
    for (int nt = 0; nt < 4; nt++)
        bOff[nt] = bl15 * B_STRIDE + (((wn * 4 + nt) ^ (bl15 & 7)) * 16);

#pragma unroll
    for (int kt = 0; kt < NKT; kt++) {
        if (kt < NKT - 1) cpa_wait<1>();
        else              cpa_wait<0>();
        __syncthreads();   // publish S_kt; retires readers of buf (kt+2)%3

        // issue S_{kt+2} into buffer (kt+2)%3 (readers ran in iter kt-1)
        if (kt + 2 < NKT) {
            int nb = (kt + 2) % NSTAGE;
            const __half* an = aptr + (kt + 2) * BK;
            cpa16(adst + nb * A_STAGE,      an);
            cpa16(adst + nb * A_STAGE + 16, an + 8);
            cpa16(adst + nb * A_STAGE + 32, an + 16);
            cpa16(adst + nb * A_STAGE + 48, an + 24);
            const __half* bn = bptr + (size_t)(kt + 2) * BK * C_CONV;
            cpa16(bdst + nb * B_STAGE + bc0, bn);
            cpa16(bdst + nb * B_STAGE + bc1, bn + 8);
            cpa16(bdst + nb * B_STAGE + bc2, bn + 16);
            cpa16(bdst + nb * B_STAGE + bc3, bn + 24);
            cpa_commit();
        }

        int buf = kt % NSTAGE;
        uint32_t aB = sbase + buf * A_STAGE;
        uint32_t bB = sbase + B_REGION + buf * B_STAGE;
#pragma unroll
        for (int ks = 0; ks < 4; ks++) {            // 4 k16 steps per stage
            uint32_t af[4][4];
#pragma unroll
            for (int mt = 0; mt < 4; mt++)
                ldmA(af[mt], aB + aOff[mt] + ks * 32);
            uint32_t bf[4][2];
#pragma unroll
            for (int nt = 0; nt < 4; nt++)
                ldmBT(bf[nt], bB + bOff[nt] + ks * (16 * B_STRIDE));
#pragma unroll
            for (int mt = 0; mt < 4; mt++)
#pragma unroll
                for (int nt = 0; nt < 4; nt++)
                    mma_f16(acc[mt][nt], af[mt], bf[nt]);
        }
    }

    // ---- epilogue: ARGMAX over rows, packed-key atomicMax (deterministic)
    // acc[mt][nt][r]: row = wm*64 + mt*16 + (lane>>2) + (r>=2 ? 8 : 0)
    //                 col = wn*32 + nt*8 + (lane&3)*2 + (r&1)
    int g = lane >> 2;
    int orow[4][2];
#pragma unroll
    for (int mt = 0; mt < 4; mt++)
#pragma unroll
        for (int h = 0; h < 2; h++) {
            int lrow = wm * 64 + mt * 16 + g + h * 8;
            orow[mt][h] = g_perm[rowstart + min(lrow, nrows - 1)];
        }
#pragma unroll
    for (int nt = 0; nt < 4; nt++) {
#pragma unroll
        for (int s = 0; s < 2; s++) {
            float v = acc[0][nt][s];
            int   bi = orow[0][0];
#pragma unroll
            for (int mt = 0; mt < 4; mt++) {
#pragma unroll
                for (int h = 0; h < 2; h++) {
                    float f = acc[mt][nt][s + 2 * h];
                    int   fi = orow[mt][h];
                    if (f > v || (f == v && fi > bi)) { v = f; bi = fi; }
                }
            }
#pragma unroll
            for (int off = 4; off <= 16; off <<= 1) {
                float fv = __shfl_xor_sync(0xffffffffu, v, off);
                int   fi = __shfl_xor_sync(0xffffffffu, bi, off);
                if (fv > v || (fv == v && fi > bi)) { v = fv; bi = fi; }
            }
            if (lane < 4) {
                int col = n0 + wn * 32 + nt * 8 + lane * 2 + s;
                atomicMax(&g_argkey[seg * C_CONV + col], packkey(v, bi));
            }
        }
    }
}

// ---------------------------------------------------------------------------
// 5. exact fp32 recompute of selected dot products (1 warp per output)
// ---------------------------------------------------------------------------
__global__ void k_exact(const float* __restrict__ feats,
                        const float* __restrict__ Wc,
                        const float* __restrict__ bcv) {
    int w = (blockIdx.x * blockDim.x + threadIdx.x) >> 5;
    if (w >= NB * C_CONV) return;
    int lane = threadIdx.x & 31;
    unsigned long long key = g_argkey[w];
    int col = w & (C_CONV - 1);
    float r;
    if (key == 0ull) {
        r = -3.0e38f;
    } else {
        int frow = (int)(unsigned)(key & 0xFFFFFFFFull);
        const float* a = feats + (size_t)frow * C_IN + lane * 8;
        float s = 0.0f;
#pragma unroll
        for (int j = 0; j < 8; j++)
            s = fmaf(a[j], Wc[(size_t)(lane * 8 + j) * C_CONV + col], s);
#pragma unroll
        for (int off = 16; off > 0; off >>= 1)
            s += __shfl_xor_sync(0xffffffffu, s, off);
        r = s + bcv[col];
    }
    if (lane == 0) g_pooled[w] = r;
}

// ---------------------------------------------------------------------------
// 6. small MLP GEMM  (M=64 fixed):  C = A[64,K] @ Bw[K,Nfull] + bias
// ---------------------------------------------------------------------------
__global__ void k_mlp(const float* __restrict__ Bw, const float* __restrict__ bias,
                      int K, int Nfull, int phase, float* __restrict__ dout) {
    const float* A = (phase == 0) ? g_pooled : g_hn;
    float* C       = (phase == 0) ? g_h : dout;

    int n0  = blockIdx.x * 64;
    int tid = threadIdx.x;
    int tx = tid & 15, ty = tid >> 4;

    __shared__ float As[64][17];
    __shared__ float Bs[16][64];

    float acc[4][4];
#pragma unroll
    for (int i = 0; i < 4; i++)
#pragma unroll
        for (int j = 0; j < 4; j++) acc[i][j] = 0.0f;

    int ar = tid >> 2, ak = (tid & 3) * 4;
    int bk = tid >> 4, bc4 = (tid & 15) * 4;

    for (int k0 = 0; k0 < K; k0 += 16) {
        __syncthreads();
        float4 av = *(const float4*)(A + (size_t)ar * K + k0 + ak);
        As[ar][ak + 0] = av.x; As[ar][ak + 1] = av.y;
        As[ar][ak + 2] = av.z; As[ar][ak + 3] = av.w;
        float4 bv = *(const float4*)(Bw + (size_t)(k0 + bk) * Nfull + n0 + bc4);
        *(float4*)&Bs[bk][bc4] = bv;
        __syncthreads();
#pragma unroll
        for (int kk = 0; kk < 16; kk++) {
            float a[4], b[4];
#pragma unroll
            for (int i = 0; i < 4; i++) a[i] = As[ty * 4 + i][kk];
#pragma unroll
            for (int j = 0; j < 4; j++) b[j] = Bs[kk][tx * 4 + j];
#pragma unroll
            for (int i = 0; i < 4; i++)
#pragma unroll
                for (int j = 0; j < 4; j++) acc[i][j] = fmaf(a[i], b[j], acc[i][j]);
        }
    }
#pragma unroll
    for (int i = 0; i < 4; i++)
#pragma unroll
        for (int j = 0; j < 4; j++)
            C[(size_t)(ty * 4 + i) * Nfull + n0 + tx * 4 + j] =
                acc[i][j] + bias[n0 + tx * 4 + j];
}

// ---------------------------------------------------------------------------
// 7. BatchNorm (training stats over B=64 rows) + ReLU : g_h -> g_hn
// ---------------------------------------------------------------------------
__global__ void k_bn(const float* __restrict__ gamma, const float* __restrict__ beta) {
    int d = blockIdx.x * blockDim.x + threadIdx.x;  // 0..1023
    float v[NB];
    float s = 0.0f;
#pragma unroll
    for (int r = 0; r < NB; r++) {
        v[r] = g_h[(size_t)r * D1 + d];
        s += v[r];
    }
    float mean = s * (1.0f / NB);
    float q = 0.0f;
#pragma unroll
    for (int r = 0; r < NB; r++) {
        float df = v[r] - mean;
        q = fmaf(df, df, q);
    }
    float var = q * (1.0f / NB);
    float sc = rsqrtf(var + 1e-5f) * gamma[d];
    float bt = beta[d];
#pragma unroll
    for (int r = 0; r < NB; r++)
        g_hn[(size_t)r * D1 + d] = fmaxf(0.0f, fmaf(v[r] - mean, sc, bt));
}

// ---------------------------------------------------------------------------
// launch
// ---------------------------------------------------------------------------
extern "C" void kernel_launch(void* const* d_in, const int* in_sizes, int n_in,
                              void* d_out, int out_size) {
    const float* feats = (const float*)d_in[0];
    const int*   bidx  = (const int*)d_in[1];
    const float* Wc    = (const float*)d_in[2];
    const float* bc    = (const float*)d_in[3];
    const float* W1    = (const float*)d_in[4];
    const float* b1    = (const float*)d_in[5];
    const float* gamma = (const float*)d_in[6];
    const float* beta  = (const float*)d_in[7];
    const float* W2    = (const float*)d_in[8];
    const float* b2    = (const float*)d_in[9];
    int N = in_sizes[1];  // number of points (batch_idx element count)
    int nblk = (N + 255) / 256;

    cudaFuncSetAttribute(k_gemm, cudaFuncAttributeMaxDynamicSharedMemorySize,
                         SMEM_DYN);

    k_histz<<<nblk, 256>>>(bidx, N);
    k_scan<<<1, 256>>>(nblk);
    k_scatcv<<<nblk, 256>>>(bidx, feats, Wc, N);

    int maxTiles = (N + BM - 1) / BM + NB;
    dim3 grid(C_CONV / BN, maxTiles);   // n-blocks fastest -> L2 reuse of A
    k_gemm<<<grid, 256, SMEM_DYN>>>();

    k_exact<<<(NB * C_CONV * 32 + 255) / 256, 256>>>(feats, Wc, bc);

    k_mlp<<<D1 / 64, 256>>>(W1, b1, C_CONV, D1, 0, nullptr);
    k_bn<<<D1 / 256, 256>>>(gamma, beta);
    k_mlp<<<D2 / 64, 256>>>(W2, b2, D1, D2, 1, (float*)d_out);
}

// round 15
// speedup vs baseline: 1.1048x; 1.1048x over previous
#include <cuda_runtime.h>
#include <cuda_fp16.h>
#include <math.h>
#include <stdint.h>

// ============================================================================
// conv1_max_embedding: feats[N,256] @ Wc[256,512] -> segment_max over batch_idx
//   -> fc1 [512,1024] -> BN(train) -> relu -> fc2 [1024,256] -> out [64,256]
//
// Strategy R15 (revert BK=64 regression; keep only the orthogonal win):
//   - R12 pipeline restored: BK=32, 4-stage cp.async, wait<2>, ONE barrier
//     per k-tile (barrier every 32 k, 2 stages in flight - measured best)
//   - NEW: hoisted ldsm address bases (targets R12's measured ALU=28.5%;
//     swizzle term loop-invariant since krow&7 == lane&7)
//   - BM=128 x BN=128, 256 thr, 2 CTAs/SM (regs 128 = full RF; hard ceiling)
//   - ARGMAX epilogue + exact fp32 recompute (bitwise-identical numerics)
// ============================================================================

#define NB 64
#define C_IN 256
#define C_CONV 512
#define D1 1024
#define D2 256
#define BM 128
#define BN 128
#define BK 32            // k per smem stage (2 mma k-steps)
#define NKT (C_IN / BK)  // 8
#define NSTAGE 4
#define MAXN 500032
#define MAXBLK (MAXN / 256 + 1)
#define MAXTILES 4160

#define A_STRIDE 80      // bytes per A smem row (32 halves=64B, padded to 80)
#define B_STRIDE 256     // bytes per B smem row (128 halves)
#define A_STAGE (BM * A_STRIDE)        // 10240
#define B_STAGE (BK * B_STRIDE)        // 8192
#define B_REGION (NSTAGE * A_STAGE)    // 40960
#define SMEM_DYN (NSTAGE * (A_STAGE + B_STAGE))   // 73728

__device__ int   g_part[MAXBLK * NB];
__device__ int   g_cursor[NB];
__device__ int   g_ntiles;
__device__ int   g_tile_seg[MAXTILES];
__device__ int   g_tile_row[MAXTILES];
__device__ int   g_tile_nrows[MAXTILES];
__device__ int   g_perm[MAXN];
__device__ unsigned long long g_argkey[NB * C_CONV];
__device__ float g_pooled[NB * C_CONV];
__device__ float g_h[NB * D1];
__device__ float g_hn[NB * D1];
__device__ __half g_afp16[(size_t)MAXN * C_IN];   // 256 MB scratch (sorted rows)
__device__ __half g_wfp16[C_IN * C_CONV];

// ---------------------------------------------------------------------------
// helpers
// ---------------------------------------------------------------------------
__device__ __forceinline__ unsigned long long packkey(float v, int row) {
    unsigned u = __float_as_uint(v);
    u = (u & 0x80000000u) ? ~u : (u | 0x80000000u);  // order-preserving map
    return ((unsigned long long)u << 32) | (unsigned)row;
}

__device__ __forceinline__ void cpa16(uint32_t dst, const void* src) {
    asm volatile("cp.async.cg.shared.global [%0], [%1], 16;"
                 :: "r"(dst), "l"(src) : "memory");
}
__device__ __forceinline__ void cpa_commit() {
    asm volatile("cp.async.commit_group;" ::: "memory");
}
template <int N>
__device__ __forceinline__ void cpa_wait() {
    asm volatile("cp.async.wait_group %0;" :: "n"(N) : "memory");
}

__device__ __forceinline__ void ldmA(uint32_t* r, uint32_t addr) {
    asm volatile("ldmatrix.sync.aligned.m8n8.x4.shared.b16 {%0,%1,%2,%3}, [%4];"
                 : "=r"(r[0]), "=r"(r[1]), "=r"(r[2]), "=r"(r[3]) : "r"(addr));
}
__device__ __forceinline__ void ldmBT(uint32_t* r, uint32_t addr) {
    asm volatile("ldmatrix.sync.aligned.m8n8.x2.trans.shared.b16 {%0,%1}, [%2];"
                 : "=r"(r[0]), "=r"(r[1]) : "r"(addr));
}
__device__ __forceinline__ void mma_f16(float* c, const uint32_t* a,
                                        const uint32_t* b) {
    asm volatile(
        "mma.sync.aligned.m16n8k16.row.col.f32.f16.f16.f32 "
        "{%0,%1,%2,%3}, {%4,%5,%6,%7}, {%8,%9}, {%0,%1,%2,%3};\n"
        : "+f"(c[0]), "+f"(c[1]), "+f"(c[2]), "+f"(c[3])
        : "r"(a[0]), "r"(a[1]), "r"(a[2]), "r"(a[3]), "r"(b[0]), "r"(b[1]));
}

__device__ __forceinline__ uint32_t pack2h(float lo, float hi) {
    __half2 h = __floats2half2_rn(lo, hi);
    return *(uint32_t*)&h;
}

// ---------------------------------------------------------------------------
// 1. partial histogram (no pre-zeroed counters) + argkey zeroing
// ---------------------------------------------------------------------------
__global__ void k_histz(const int* __restrict__ bidx, int N) {
    __shared__ int lc[NB];
    int t = threadIdx.x;
    if (t < NB) lc[t] = 0;
    for (int j = blockIdx.x * 256 + t; j < NB * C_CONV; j += gridDim.x * 256)
        g_argkey[j] = 0ull;
    __syncthreads();
    int i = blockIdx.x * 256 + t;
    if (i < N) atomicAdd(&lc[bidx[i]], 1);
    __syncthreads();
    if (t < NB) g_part[blockIdx.x * NB + t] = lc[t];
}

// ---------------------------------------------------------------------------
// 2. sum partials + prefix scan + tile table (single block, 256 threads)
// ---------------------------------------------------------------------------
__global__ void k_scan(int nblk) {
    __shared__ int part4[4][NB];
    __shared__ int cnt[NB], sbase[NB], stb[NB];
    int t = threadIdx.x;            // 256
    int seg = t & 63, q = t >> 6;
    int s = 0;
    for (int b = q; b < nblk; b += 4) s += g_part[b * NB + seg];
    part4[q][seg] = s;
    __syncthreads();
    if (t < NB)
        cnt[t] = part4[0][t] + part4[1][t] + part4[2][t] + part4[3][t];
    __syncthreads();
    if (t == 0) {
        int acc = 0, ta = 0;
        for (int g = 0; g < NB; g++) {
            sbase[g] = acc; acc += cnt[g];
            stb[g] = ta;    ta += (cnt[g] + BM - 1) >> 7;
        }
        g_ntiles = ta;
    }
    __syncthreads();
    if (t < NB) {
        g_cursor[t] = sbase[t];
        int nt = (cnt[t] + BM - 1) >> 7;
        for (int i = 0; i < nt; i++) {
            int id = stb[t] + i;
            g_tile_seg[id]   = t;
            g_tile_row[id]   = sbase[t] + i * BM;
            g_tile_nrows[id] = min(BM, cnt[t] - i * BM);
        }
    }
}

// ---------------------------------------------------------------------------
// 3. scatter + gather-convert feats to sorted fp16 + convert Wc
// ---------------------------------------------------------------------------
__global__ void k_scatcv(const int* __restrict__ bidx,
                         const float* __restrict__ feats,
                         const float* __restrict__ Wc, int N) {
    __shared__ int lc[NB], lbase[NB];
    __shared__ int sdst[256];
    int t = threadIdx.x;
    if (t < NB) lc[t] = 0;
    __syncthreads();
    int i = blockIdx.x * 256 + t;
    int b = 0, rank = 0;
    if (i < N) {
        b = bidx[i];
        rank = atomicAdd(&lc[b], 1);
    }
    __syncthreads();
    if (t < NB && lc[t] > 0) lbase[t] = atomicAdd(&g_cursor[t], lc[t]);
    __syncthreads();
    int dst = 0;
    if (i < N) {
        dst = lbase[b] + rank;
        g_perm[dst] = i;
    }
    sdst[t] = dst;
    __syncthreads();
    int lane = t & 31, w = t >> 5;
    for (int p = w; p < 256; p += 8) {
        int src = blockIdx.x * 256 + p;
        if (src >= N) break;
        int d = sdst[p];
        const float4* sp = (const float4*)(feats + (size_t)src * C_IN + lane * 8);
        float4 x = sp[0], y = sp[1];
        uint4 o = make_uint4(pack2h(x.x, x.y), pack2h(x.z, x.w),
                             pack2h(y.x, y.y), pack2h(y.z, y.w));
        *(uint4*)(g_afp16 + (size_t)d * C_IN + lane * 8) = o;
    }
    if (blockIdx.x < 64) {
        int j = (blockIdx.x * 256 + t) * 8;
        const float4* sp = (const float4*)(Wc + j);
        float4 x = sp[0], y = sp[1];
        uint4 o = make_uint4(pack2h(x.x, x.y), pack2h(x.z, x.w),
                             pack2h(y.x, y.y), pack2h(y.z, y.w));
        *(uint4*)(g_wfp16 + j) = o;
    }
}

// ---------------------------------------------------------------------------
// 4. FP16 tensor GEMM, BM=128 x BN=128, 256 threads, BK=32, 4-stage cp.async,
//    one barrier per k-tile, 2 CTAs/SM. Hoisted ldsm bases. ARGMAX epilogue.
//    8 warps (2m x 4n); warp tile 64x32 (mt<4, nt<4)
// ---------------------------------------------------------------------------
__global__ void __launch_bounds__(256, 2)
k_gemm() {
    int tile = blockIdx.y;
    if (tile >= g_ntiles) return;
    int seg      = g_tile_seg[tile];
    int rowstart = g_tile_row[tile];
    int nrows    = g_tile_nrows[tile];
    int n0       = blockIdx.x * BN;

    extern __shared__ __align__(128) char dsm[];

    int tid  = threadIdx.x;
    int lane = tid & 31, wid = tid >> 5;
    int wm = wid & 1, wn = wid >> 1;   // 2 x 4 warp grid

    uint32_t sbase = (uint32_t)__cvta_generic_to_shared(dsm);

    // ---- A copy mapping: 2 threads per row, 16 halves (2x16B) each
    int ar  = tid >> 1;                 // 0..127
    int akh = tid & 1;
    const __half* aptr =
        g_afp16 + (size_t)(rowstart + min(ar, nrows - 1)) * C_IN + akh * 16;
    uint32_t adst = sbase + ar * A_STRIDE + akh * 32;
    // ---- B copy mapping: 8 threads per k-row, 16 halves (2 chunks) each
    int bk  = tid >> 3;                 // 0..31 k row within stage
    int bnc = tid & 7;
    const __half* bptr = g_wfp16 + (size_t)bk * C_CONV + n0 + bnc * 16;
    int c0 = (bnc * 2)     ^ (bk & 7);
    int c1 = (bnc * 2 + 1) ^ (bk & 7);
    uint32_t bdst = sbase + B_REGION + bk * B_STRIDE;

    float acc[4][4][4];
#pragma unroll
    for (int mt = 0; mt < 4; mt++)
#pragma unroll
        for (int nt = 0; nt < 4; nt++)
#pragma unroll
            for (int r = 0; r < 4; r++) acc[mt][nt][r] = 0.0f;

    // ---- prologue: issue stages 0..2
#pragma unroll
    for (int s = 0; s < NSTAGE - 1; s++) {
        const __half* an = aptr + s * BK;
        cpa16(adst + s * A_STAGE, an);
        cpa16(adst + s * A_STAGE + 16, an + 8);
        const __half* bn = bptr + (size_t)s * BK * C_CONV;
        cpa16(bdst + s * B_STAGE + c0 * 16, bn);
        cpa16(bdst + s * B_STAGE + c1 * 16, bn + 8);
        cpa_commit();
    }

    // ---- hoisted ldsm address bases (loop-invariant; krow&7 == lane&7)
    int asub = lane >> 3, al7 = lane & 7;
    int arow_frag = (asub & 1) * 8 + al7;
    int akoff = (asub >> 1) * 16;
    int bl15 = lane & 15;
    int aOff[4], bOff[4];
#pragma unroll
    for (int mt = 0; mt < 4; mt++)
        aOff[mt] = (wm * 64 + mt * 16 + arow_frag) * A_STRIDE + akoff;
#pragma unroll
    for (int nt = 0; nt < 4; nt++)
        bOff[nt] = bl15 * B_STRIDE + (((wn * 4 + nt) ^ (bl15 & 7)) * 16);

#pragma unroll
    for (int kt = 0; kt < NKT; kt++) {
        // ensure S_kt landed (in-flight at this point: S_kt..min(kt+2,NKT-1))
        if (kt <= NKT - 3)      cpa_wait<2>();
        else if (kt == NKT - 2) cpa_wait<1>();
        else                    cpa_wait<0>();
        __syncthreads();   // publish S_kt; retires readers of buf (kt+3)%4

        // issue S_{kt+3} into buffer (kt+3)%4 (readers ran in iter kt-1)
        if (kt + 3 < NKT) {
            int nb = (kt + 3) % NSTAGE;
            const __half* an = aptr + (kt + 3) * BK;
            cpa16(adst + nb * A_STAGE, an);
            cpa16(adst + nb * A_STAGE + 16, an + 8);
            const __half* bn = bptr + (size_t)(kt + 3) * BK * C_CONV;
            cpa16(bdst + nb * B_STAGE + c0 * 16, bn);
            cpa16(bdst + nb * B_STAGE + c1 * 16, bn + 8);
            cpa_commit();
        }

        int buf = kt % NSTAGE;
        uint32_t aB = sbase + buf * A_STAGE;
        uint32_t bB = sbase + B_REGION + buf * B_STAGE;
#pragma unroll
        for (int ks = 0; ks < 2; ks++) {
            uint32_t af[4][4];
#pragma unroll
            for (int mt = 0; mt < 4; mt++)
                ldmA(af[mt], aB + aOff[mt] + ks * 32);
            uint32_t bf[4][2];
#pragma unroll
            for (int nt = 0; nt < 4; nt++)
                ldmBT(bf[nt], bB + bOff[nt] + ks * (16 * B_STRIDE));
#pragma unroll
            for (int mt = 0; mt < 4; mt++)
#pragma unroll
                for (int nt = 0; nt < 4; nt++)
                    mma_f16(acc[mt][nt], af[mt], bf[nt]);
        }
    }

    // ---- epilogue: ARGMAX over rows, packed-key atomicMax (deterministic)
    // acc[mt][nt][r]: row = wm*64 + mt*16 + (lane>>2) + (r>=2 ? 8 : 0)
    //                 col = wn*32 + nt*8 + (lane&3)*2 + (r&1)
    int g = lane >> 2;
    int orow[4][2];
#pragma unroll
    for (int mt = 0; mt < 4; mt++)
#pragma unroll
        for (int h = 0; h < 2; h++) {
            int lrow = wm * 64 + mt * 16 + g + h * 8;
            orow[mt][h] = g_perm[rowstart + min(lrow, nrows - 1)];
        }
#pragma unroll
    for (int nt = 0; nt < 4; nt++) {
#pragma unroll
        for (int s = 0; s < 2; s++) {
            float v = acc[0][nt][s];
            int   bi = orow[0][0];
#pragma unroll
            for (int mt = 0; mt < 4; mt++) {
#pragma unroll
                for (int h = 0; h < 2; h++) {
                    float f = acc[mt][nt][s + 2 * h];
                    int   fi = orow[mt][h];
                    if (f > v || (f == v && fi > bi)) { v = f; bi = fi; }
                }
            }
#pragma unroll
            for (int off = 4; off <= 16; off <<= 1) {
                float fv = __shfl_xor_sync(0xffffffffu, v, off);
                int   fi = __shfl_xor_sync(0xffffffffu, bi, off);
                if (fv > v || (fv == v && fi > bi)) { v = fv; bi = fi; }
            }
            if (lane < 4) {
                int col = n0 + wn * 32 + nt * 8 + lane * 2 + s;
                atomicMax(&g_argkey[seg * C_CONV + col], packkey(v, bi));
            }
        }
    }
}

// ---------------------------------------------------------------------------
// 5. exact fp32 recompute of selected dot products (1 warp per output)
// ---------------------------------------------------------------------------
__global__ void k_exact(const float* __restrict__ feats,
                        const float* __restrict__ Wc,
                        const float* __restrict__ bcv) {
    int w = (blockIdx.x * blockDim.x + threadIdx.x) >> 5;
    if (w >= NB * C_CONV) return;
    int lane = threadIdx.x & 31;
    unsigned long long key = g_argkey[w];
    int col = w & (C_CONV - 1);
    float r;
    if (key == 0ull) {
        r = -3.0e38f;
    } else {
        int frow = (int)(unsigned)(key & 0xFFFFFFFFull);
        const float* a = feats + (size_t)frow * C_IN + lane * 8;
        float s = 0.0f;
#pragma unroll
        for (int j = 0; j < 8; j++)
            s = fmaf(a[j], Wc[(size_t)(lane * 8 + j) * C_CONV + col], s);
#pragma unroll
        for (int off = 16; off > 0; off >>= 1)
            s += __shfl_xor_sync(0xffffffffu, s, off);
        r = s + bcv[col];
    }
    if (lane == 0) g_pooled[w] = r;
}

// ---------------------------------------------------------------------------
// 6. small MLP GEMM  (M=64 fixed):  C = A[64,K] @ Bw[K,Nfull] + bias
// ---------------------------------------------------------------------------
__global__ void k_mlp(const float* __restrict__ Bw, const float* __restrict__ bias,
                      int K, int Nfull, int phase, float* __restrict__ dout) {
    const float* A = (phase == 0) ? g_pooled : g_hn;
    float* C       = (phase == 0) ? g_h : dout;

    int n0  = blockIdx.x * 64;
    int tid = threadIdx.x;
    int tx = tid & 15, ty = tid >> 4;

    __shared__ float As[64][17];
    __shared__ float Bs[16][64];

    float acc[4][4];
#pragma unroll
    for (int i = 0; i < 4; i++)
#pragma unroll
        for (int j = 0; j < 4; j++) acc[i][j] = 0.0f;

    int ar = tid >> 2, ak = (tid & 3) * 4;
    int bk = tid >> 4, bc4 = (tid & 15) * 4;

    for (int k0 = 0; k0 < K; k0 += 16) {
        __syncthreads();
        float4 av = *(const float4*)(A + (size_t)ar * K + k0 + ak);
        As[ar][ak + 0] = av.x; As[ar][ak + 1] = av.y;
        As[ar][ak + 2] = av.z; As[ar][ak + 3] = av.w;
        float4 bv = *(const float4*)(Bw + (size_t)(k0 + bk) * Nfull + n0 + bc4);
        *(float4*)&Bs[bk][bc4] = bv;
        __syncthreads();
#pragma unroll
        for (int kk = 0; kk < 16; kk++) {
            float a[4], b[4];
#pragma unroll
            for (int i = 0; i < 4; i++) a[i] = As[ty * 4 + i][kk];
#pragma unroll
            for (int j = 0; j < 4; j++) b[j] = Bs[kk][tx * 4 + j];
#pragma unroll
            for (int i = 0; i < 4; i++)
#pragma unroll
                for (int j = 0; j < 4; j++) acc[i][j] = fmaf(a[i], b[j], acc[i][j]);
        }
    }
#pragma unroll
    for (int i = 0; i < 4; i++)
#pragma unroll
        for (int j = 0; j < 4; j++)
            C[(size_t)(ty * 4 + i) * Nfull + n0 + tx * 4 + j] =
                acc[i][j] + bias[n0 + tx * 4 + j];
}

// ---------------------------------------------------------------------------
// 7. BatchNorm (training stats over B=64 rows) + ReLU : g_h -> g_hn
// ---------------------------------------------------------------------------
__global__ void k_bn(const float* __restrict__ gamma, const float* __restrict__ beta) {
    int d = blockIdx.x * blockDim.x + threadIdx.x;  // 0..1023
    float v[NB];
    float s = 0.0f;
#pragma unroll
    for (int r = 0; r < NB; r++) {
        v[r] = g_h[(size_t)r * D1 + d];
        s += v[r];
    }
    float mean = s * (1.0f / NB);
    float q = 0.0f;
#pragma unroll
    for (int r = 0; r < NB; r++) {
        float df = v[r] - mean;
        q = fmaf(df, df, q);
    }
    float var = q * (1.0f / NB);
    float sc = rsqrtf(var + 1e-5f) * gamma[d];
    float bt = beta[d];
#pragma unroll
    for (int r = 0; r < NB; r++)
        g_hn[(size_t)r * D1 + d] = fmaxf(0.0f, fmaf(v[r] - mean, sc, bt));
}

// ---------------------------------------------------------------------------
// launch
// ---------------------------------------------------------------------------
extern "C" void kernel_launch(void* const* d_in, const int* in_sizes, int n_in,
                              void* d_out, int out_size) {
    const float* feats = (const float*)d_in[0];
    const int*   bidx  = (const int*)d_in[1];
    const float* Wc    = (const float*)d_in[2];
    const float* bc    = (const float*)d_in[3];
    const float* W1    = (const float*)d_in[4];
    const float* b1    = (const float*)d_in[5];
    const float* gamma = (const float*)d_in[6];
    const float* beta  = (const float*)d_in[7];
    const float* W2    = (const float*)d_in[8];
    const float* b2    = (const float*)d_in[9];
    int N = in_sizes[1];  // number of points (batch_idx element count)
    int nblk = (N + 255) / 256;

    cudaFuncSetAttribute(k_gemm, cudaFuncAttributeMaxDynamicSharedMemorySize,
                         SMEM_DYN);

    k_histz<<<nblk, 256>>>(bidx, N);
    k_scan<<<1, 256>>>(nblk);
    k_scatcv<<<nblk, 256>>>(bidx, feats, Wc, N);

    int maxTiles = (N + BM - 1) / BM + NB;
    dim3 grid(C_CONV / BN, maxTiles);   // n-blocks fastest -> L2 reuse of A
    k_gemm<<<grid, 256, SMEM_DYN>>>();

    k_exact<<<(NB * C_CONV * 32 + 255) / 256, 256>>>(feats, Wc, bc);

    k_mlp<<<D1 / 64, 256>>>(W1, b1, C_CONV, D1, 0, nullptr);
    k_bn<<<D1 / 256, 256>>>(gamma, beta);
    k_mlp<<<D2 / 64, 256>>>(W2, b2, D1, D2, 1, (float*)d_out);
}

// round 16
// speedup vs baseline: 1.1142x; 1.0085x over previous
#include <cuda_runtime.h>
#include <cuda_fp16.h>
#include <math.h>
#include <stdint.h>

// ============================================================================
// conv1_max_embedding: feats[N,256] @ Wc[256,512] -> segment_max over batch_idx
//   -> fc1 [512,1024] -> BN(train) -> relu -> fc2 [1024,256] -> out [64,256]
//
// Strategy R16 (profile: GEMM at floor ~480; attack the ~330us non-GEMM):
//   - k_exact rewritten thread-per-output: Wc coalesced (was 2KB-strided),
//     ~268MB effective traffic -> ~32MB
//   - GEMM: R12/R15 pipeline (BK=32, barrier/32k) with NSTAGE 4->5 for
//     extra prefetch slack; inner loop untouched (measured at floor)
//   - ARGMAX epilogue + exact fp32 recompute unchanged in structure
// ============================================================================

#define NB 64
#define C_IN 256
#define C_CONV 512
#define D1 1024
#define D2 256
#define BM 128
#define BN 128
#define BK 32            // k per smem stage (2 mma k-steps)
#define NKT (C_IN / BK)  // 8
#define NSTAGE 5
#define MAXN 500032
#define MAXBLK (MAXN / 256 + 1)
#define MAXTILES 4160

#define A_STRIDE 80      // bytes per A smem row (32 halves=64B, padded to 80)
#define B_STRIDE 256     // bytes per B smem row (128 halves)
#define A_STAGE (BM * A_STRIDE)        // 10240
#define B_STAGE (BK * B_STRIDE)        // 8192
#define B_REGION (NSTAGE * A_STAGE)    // 51200
#define SMEM_DYN (NSTAGE * (A_STAGE + B_STAGE))   // 92160

__device__ int   g_part[MAXBLK * NB];
__device__ int   g_cursor[NB];
__device__ int   g_ntiles;
__device__ int   g_tile_seg[MAXTILES];
__device__ int   g_tile_row[MAXTILES];
__device__ int   g_tile_nrows[MAXTILES];
__device__ int   g_perm[MAXN];
__device__ unsigned long long g_argkey[NB * C_CONV];
__device__ float g_pooled[NB * C_CONV];
__device__ float g_h[NB * D1];
__device__ float g_hn[NB * D1];
__device__ __half g_afp16[(size_t)MAXN * C_IN];   // 256 MB scratch (sorted rows)
__device__ __half g_wfp16[C_IN * C_CONV];

// ---------------------------------------------------------------------------
// helpers
// ---------------------------------------------------------------------------
__device__ __forceinline__ unsigned long long packkey(float v, int row) {
    unsigned u = __float_as_uint(v);
    u = (u & 0x80000000u) ? ~u : (u | 0x80000000u);  // order-preserving map
    return ((unsigned long long)u << 32) | (unsigned)row;
}

__device__ __forceinline__ void cpa16(uint32_t dst, const void* src) {
    asm volatile("cp.async.cg.shared.global [%0], [%1], 16;"
                 :: "r"(dst), "l"(src) : "memory");
}
__device__ __forceinline__ void cpa_commit() {
    asm volatile("cp.async.commit_group;" ::: "memory");
}
template <int N>
__device__ __forceinline__ void cpa_wait() {
    asm volatile("cp.async.wait_group %0;" :: "n"(N) : "memory");
}

__device__ __forceinline__ void ldmA(uint32_t* r, uint32_t addr) {
    asm volatile("ldmatrix.sync.aligned.m8n8.x4.shared.b16 {%0,%1,%2,%3}, [%4];"
                 : "=r"(r[0]), "=r"(r[1]), "=r"(r[2]), "=r"(r[3]) : "r"(addr));
}
__device__ __forceinline__ void ldmBT(uint32_t* r, uint32_t addr) {
    asm volatile("ldmatrix.sync.aligned.m8n8.x2.trans.shared.b16 {%0,%1}, [%2];"
                 : "=r"(r[0]), "=r"(r[1]) : "r"(addr));
}
__device__ __forceinline__ void mma_f16(float* c, const uint32_t* a,
                                        const uint32_t* b) {
    asm volatile(
        "mma.sync.aligned.m16n8k16.row.col.f32.f16.f16.f32 "
        "{%0,%1,%2,%3}, {%4,%5,%6,%7}, {%8,%9}, {%0,%1,%2,%3};\n"
        : "+f"(c[0]), "+f"(c[1]), "+f"(c[2]), "+f"(c[3])
        : "r"(a[0]), "r"(a[1]), "r"(a[2]), "r"(a[3]), "r"(b[0]), "r"(b[1]));
}

__device__ __forceinline__ uint32_t pack2h(float lo, float hi) {
    __half2 h = __floats2half2_rn(lo, hi);
    return *(uint32_t*)&h;
}

// ---------------------------------------------------------------------------
// 1. partial histogram (no pre-zeroed counters) + argkey zeroing
// ---------------------------------------------------------------------------
__global__ void k_histz(const int* __restrict__ bidx, int N) {
    __shared__ int lc[NB];
    int t = threadIdx.x;
    if (t < NB) lc[t] = 0;
    for (int j = blockIdx.x * 256 + t; j < NB * C_CONV; j += gridDim.x * 256)
        g_argkey[j] = 0ull;
    __syncthreads();
    int i = blockIdx.x * 256 + t;
    if (i < N) atomicAdd(&lc[bidx[i]], 1);
    __syncthreads();
    if (t < NB) g_part[blockIdx.x * NB + t] = lc[t];
}

// ---------------------------------------------------------------------------
// 2. sum partials + prefix scan + tile table (single block, 256 threads)
// ---------------------------------------------------------------------------
__global__ void k_scan(int nblk) {
    __shared__ int part4[4][NB];
    __shared__ int cnt[NB], sbase[NB], stb[NB];
    int t = threadIdx.x;            // 256
    int seg = t & 63, q = t >> 6;
    int s = 0;
    for (int b = q; b < nblk; b += 4) s += g_part[b * NB + seg];
    part4[q][seg] = s;
    __syncthreads();
    if (t < NB)
        cnt[t] = part4[0][t] + part4[1][t] + part4[2][t] + part4[3][t];
    __syncthreads();
    if (t == 0) {
        int acc = 0, ta = 0;
        for (int g = 0; g < NB; g++) {
            sbase[g] = acc; acc += cnt[g];
            stb[g] = ta;    ta += (cnt[g] + BM - 1) >> 7;
        }
        g_ntiles = ta;
    }
    __syncthreads();
    if (t < NB) {
        g_cursor[t] = sbase[t];
        int nt = (cnt[t] + BM - 1) >> 7;
        for (int i = 0; i < nt; i++) {
            int id = stb[t] + i;
            g_tile_seg[id]   = t;
            g_tile_row[id]   = sbase[t] + i * BM;
            g_tile_nrows[id] = min(BM, cnt[t] - i * BM);
        }
    }
}

// ---------------------------------------------------------------------------
// 3. scatter + gather-convert feats to sorted fp16 + convert Wc
// ---------------------------------------------------------------------------
__global__ void k_scatcv(const int* __restrict__ bidx,
                         const float* __restrict__ feats,
                         const float* __restrict__ Wc, int N) {
    __shared__ int lc[NB], lbase[NB];
    __shared__ int sdst[256];
    int t = threadIdx.x;
    if (t < NB) lc[t] = 0;
    __syncthreads();
    int i = blockIdx.x * 256 + t;
    int b = 0, rank = 0;
    if (i < N) {
        b = bidx[i];
        rank = atomicAdd(&lc[b], 1);
    }
    __syncthreads();
    if (t < NB && lc[t] > 0) lbase[t] = atomicAdd(&g_cursor[t], lc[t]);
    __syncthreads();
    int dst = 0;
    if (i < N) {
        dst = lbase[b] + rank;
        g_perm[dst] = i;
    }
    sdst[t] = dst;
    __syncthreads();
    int lane = t & 31, w = t >> 5;
    for (int p = w; p < 256; p += 8) {
        int src = blockIdx.x * 256 + p;
        if (src >= N) break;
        int d = sdst[p];
        const float4* sp = (const float4*)(feats + (size_t)src * C_IN + lane * 8);
        float4 x = sp[0], y = sp[1];
        uint4 o = make_uint4(pack2h(x.x, x.y), pack2h(x.z, x.w),
                             pack2h(y.x, y.y), pack2h(y.z, y.w));
        *(uint4*)(g_afp16 + (size_t)d * C_IN + lane * 8) = o;
    }
    if (blockIdx.x < 64) {
        int j = (blockIdx.x * 256 + t) * 8;
        const float4* sp = (const float4*)(Wc + j);
        float4 x = sp[0], y = sp[1];
        uint4 o = make_uint4(pack2h(x.x, x.y), pack2h(x.z, x.w),
                             pack2h(y.x, y.y), pack2h(y.z, y.w));
        *(uint4*)(g_wfp16 + j) = o;
    }
}

// ---------------------------------------------------------------------------
// 4. FP16 tensor GEMM, BM=128 x BN=128, 256 threads, BK=32, 5-stage cp.async,
//    one barrier per k-tile, 2 CTAs/SM. ARGMAX epilogue.
//    8 warps (2m x 4n); warp tile 64x32 (mt<4, nt<4)
// ---------------------------------------------------------------------------
__global__ void __launch_bounds__(256, 2)
k_gemm() {
    int tile = blockIdx.y;
    if (tile >= g_ntiles) return;
    int seg      = g_tile_seg[tile];
    int rowstart = g_tile_row[tile];
    int nrows    = g_tile_nrows[tile];
    int n0       = blockIdx.x * BN;

    extern __shared__ __align__(128) char dsm[];

    int tid  = threadIdx.x;
    int lane = tid & 31, wid = tid >> 5;
    int wm = wid & 1, wn = wid >> 1;   // 2 x 4 warp grid

    uint32_t sbase = (uint32_t)__cvta_generic_to_shared(dsm);

    // ---- A copy mapping: 2 threads per row, 16 halves (2x16B) each
    int ar  = tid >> 1;                 // 0..127
    int akh = tid & 1;
    const __half* aptr =
        g_afp16 + (size_t)(rowstart + min(ar, nrows - 1)) * C_IN + akh * 16;
    uint32_t adst = sbase + ar * A_STRIDE + akh * 32;
    // ---- B copy mapping: 8 threads per k-row, 16 halves (2 chunks) each
    int bk  = tid >> 3;                 // 0..31 k row within stage
    int bnc = tid & 7;
    const __half* bptr = g_wfp16 + (size_t)bk * C_CONV + n0 + bnc * 16;
    int c0 = (bnc * 2)     ^ (bk & 7);
    int c1 = (bnc * 2 + 1) ^ (bk & 7);
    uint32_t bdst = sbase + B_REGION + bk * B_STRIDE;

    float acc[4][4][4];
#pragma unroll
    for (int mt = 0; mt < 4; mt++)
#pragma unroll
        for (int nt = 0; nt < 4; nt++)
#pragma unroll
            for (int r = 0; r < 4; r++) acc[mt][nt][r] = 0.0f;

    // ---- prologue: issue stages 0..3
#pragma unroll
    for (int s = 0; s < NSTAGE - 1; s++) {
        const __half* an = aptr + s * BK;
        cpa16(adst + s * A_STAGE, an);
        cpa16(adst + s * A_STAGE + 16, an + 8);
        const __half* bn = bptr + (size_t)s * BK * C_CONV;
        cpa16(bdst + s * B_STAGE + c0 * 16, bn);
        cpa16(bdst + s * B_STAGE + c1 * 16, bn + 8);
        cpa_commit();
    }

    // ---- ldsm lane addressing
    int asub = lane >> 3, al7 = lane & 7;
    int arow_frag = (asub & 1) * 8 + al7;
    int akoff = (asub >> 1) * 16;
    int bl15 = lane & 15;
    int aOff[4], bOff[4];
#pragma unroll
    for (int mt = 0; mt < 4; mt++)
        aOff[mt] = (wm * 64 + mt * 16 + arow_frag) * A_STRIDE + akoff;
#pragma unroll
    for (int nt = 0; nt < 4; nt++)
        bOff[nt] = bl15 * B_STRIDE + (((wn * 4 + nt) ^ (bl15 & 7)) * 16);

#pragma unroll
    for (int kt = 0; kt < NKT; kt++) {
        // ensure S_kt landed (groups in flight: min(NKT,kt+4) - kt)
        if (kt <= NKT - 5)      cpa_wait<3>();
        else if (kt == NKT - 4) cpa_wait<3>();
        else if (kt == NKT - 3) cpa_wait<2>();
        else if (kt == NKT - 2) cpa_wait<1>();
        else                    cpa_wait<0>();
        __syncthreads();   // publish S_kt; retires readers of buf (kt+4)%5

        // issue S_{kt+4} into buffer (kt+4)%5 (readers ran in iter kt-1)
        if (kt + 4 < NKT) {
            int nb = (kt + 4) % NSTAGE;
            const __half* an = aptr + (kt + 4) * BK;
            cpa16(adst + nb * A_STAGE, an);
            cpa16(adst + nb * A_STAGE + 16, an + 8);
            const __half* bn = bptr + (size_t)(kt + 4) * BK * C_CONV;
            cpa16(bdst + nb * B_STAGE + c0 * 16, bn);
            cpa16(bdst + nb * B_STAGE + c1 * 16, bn + 8);
            cpa_commit();
        }

        int buf = kt % NSTAGE;
        uint32_t aB = sbase + buf * A_STAGE;
        uint32_t bB = sbase + B_REGION + buf * B_STAGE;
#pragma unroll
        for (int ks = 0; ks < 2; ks++) {
            uint32_t af[4][4];
#pragma unroll
            for (int mt = 0; mt < 4; mt++)
                ldmA(af[mt], aB + aOff[mt] + ks * 32);
            uint32_t bf[4][2];
#pragma unroll
            for (int nt = 0; nt < 4; nt++)
                ldmBT(bf[nt], bB + bOff[nt] + ks * (16 * B_STRIDE));
#pragma unroll
            for (int mt = 0; mt < 4; mt++)
#pragma unroll
                for (int nt = 0; nt < 4; nt++)
                    mma_f16(acc[mt][nt], af[mt], bf[nt]);
        }
    }

    // ---- epilogue: ARGMAX over rows, packed-key atomicMax (deterministic)
    int g = lane >> 2;
    int orow[4][2];
#pragma unroll
    for (int mt = 0; mt < 4; mt++)
#pragma unroll
        for (int h = 0; h < 2; h++) {
            int lrow = wm * 64 + mt * 16 + g + h * 8;
            orow[mt][h] = g_perm[rowstart + min(lrow, nrows - 1)];
        }
#pragma unroll
    for (int nt = 0; nt < 4; nt++) {
#pragma unroll
        for (int s = 0; s < 2; s++) {
            float v = acc[0][nt][s];
            int   bi = orow[0][0];
#pragma unroll
            for (int mt = 0; mt < 4; mt++) {
#pragma unroll
                for (int h = 0; h < 2; h++) {
                    float f = acc[mt][nt][s + 2 * h];
                    int   fi = orow[mt][h];
                    if (f > v || (f == v && fi > bi)) { v = f; bi = fi; }
                }
            }
#pragma unroll
            for (int off = 4; off <= 16; off <<= 1) {
                float fv = __shfl_xor_sync(0xffffffffu, v, off);
                int   fi = __shfl_xor_sync(0xffffffffu, bi, off);
                if (fv > v || (fv == v && fi > bi)) { v = fv; bi = fi; }
            }
            if (lane < 4) {
                int col = n0 + wn * 32 + nt * 8 + lane * 2 + s;
                atomicMax(&g_argkey[seg * C_CONV + col], packkey(v, bi));
            }
        }
    }
}

// ---------------------------------------------------------------------------
// 5. exact fp32 recompute, THREAD per output (Wc coalesced across threads)
// ---------------------------------------------------------------------------
__global__ void k_exact(const float* __restrict__ feats,
                        const float* __restrict__ Wc,
                        const float* __restrict__ bcv) {
    int w = blockIdx.x * blockDim.x + threadIdx.x;   // w = seg*512 + col
    if (w >= NB * C_CONV) return;
    int col = w & (C_CONV - 1);
    unsigned long long key = g_argkey[w];
    if (key == 0ull) { g_pooled[w] = -3.0e38f; return; }
    int frow = (int)(unsigned)(key & 0xFFFFFFFFull);
    const float* a = feats + (size_t)frow * C_IN;
    const float* wcol = Wc + col;
    float s0 = 0.0f, s1 = 0.0f;
#pragma unroll 4
    for (int k = 0; k < C_IN; k += 8) {
        float4 x = *(const float4*)(a + k);
        float4 y = *(const float4*)(a + k + 4);
        s0 = fmaf(x.x, wcol[(size_t)(k + 0) * C_CONV], s0);
        s1 = fmaf(x.y, wcol[(size_t)(k + 1) * C_CONV], s1);
        s0 = fmaf(x.z, wcol[(size_t)(k + 2) * C_CONV], s0);
        s1 = fmaf(x.w, wcol[(size_t)(k + 3) * C_CONV], s1);
        s0 = fmaf(y.x, wcol[(size_t)(k + 4) * C_CONV], s0);
        s1 = fmaf(y.y, wcol[(size_t)(k + 5) * C_CONV], s1);
        s0 = fmaf(y.z, wcol[(size_t)(k + 6) * C_CONV], s0);
        s1 = fmaf(y.w, wcol[(size_t)(k + 7) * C_CONV], s1);
    }
    g_pooled[w] = s0 + s1 + bcv[col];
}

// ---------------------------------------------------------------------------
// 6. small MLP GEMM  (M=64 fixed):  C = A[64,K] @ Bw[K,Nfull] + bias
// ---------------------------------------------------------------------------
__global__ void k_mlp(const float* __restrict__ Bw, const float* __restrict__ bias,
                      int K, int Nfull, int phase, float* __restrict__ dout) {
    const float* A = (phase == 0) ? g_pooled : g_hn;
    float* C       = (phase == 0) ? g_h : dout;

    int n0  = blockIdx.x * 64;
    int tid = threadIdx.x;
    int tx = tid & 15, ty = tid >> 4;

    __shared__ float As[64][17];
    __shared__ float Bs[16][64];

    float acc[4][4];
#pragma unroll
    for (int i = 0; i < 4; i++)
#pragma unroll
        for (int j = 0; j < 4; j++) acc[i][j] = 0.0f;

    int ar = tid >> 2, ak = (tid & 3) * 4;
    int bk = tid >> 4, bc4 = (tid & 15) * 4;

    for (int k0 = 0; k0 < K; k0 += 16) {
        __syncthreads();
        float4 av = *(const float4*)(A + (size_t)ar * K + k0 + ak);
        As[ar][ak + 0] = av.x; As[ar][ak + 1] = av.y;
        As[ar][ak + 2] = av.z; As[ar][ak + 3] = av.w;
        float4 bv = *(const float4*)(Bw + (size_t)(k0 + bk) * Nfull + n0 + bc4);
        *(float4*)&Bs[bk][bc4] = bv;
        __syncthreads();
#pragma unroll
        for (int kk = 0; kk < 16; kk++) {
            float a[4], b[4];
#pragma unroll
            for (int i = 0; i < 4; i++) a[i] = As[ty * 4 + i][kk];
#pragma unroll
            for (int j = 0; j < 4; j++) b[j] = Bs[kk][tx * 4 + j];
#pragma unroll
            for (int i = 0; i < 4; i++)
#pragma unroll
                for (int j = 0; j < 4; j++) acc[i][j] = fmaf(a[i], b[j], acc[i][j]);
        }
    }
#pragma unroll
    for (int i = 0; i < 4; i++)
#pragma unroll
        for (int j = 0; j < 4; j++)
            C[(size_t)(ty * 4 + i) * Nfull + n0 + tx * 4 + j] =
                acc[i][j] + bias[n0 + tx * 4 + j];
}

// ---------------------------------------------------------------------------
// 7. BatchNorm (training stats over B=64 rows) + ReLU : g_h -> g_hn
// ---------------------------------------------------------------------------
__global__ void k_bn(const float* __restrict__ gamma, const float* __restrict__ beta) {
    int d = blockIdx.x * blockDim.x + threadIdx.x;  // 0..1023
    float v[NB];
    float s = 0.0f;
#pragma unroll
    for (int r = 0; r < NB; r++) {
        v[r] = g_h[(size_t)r * D1 + d];
        s += v[r];
    }
    float mean = s * (1.0f / NB);
    float q = 0.0f;
#pragma unroll
    for (int r = 0; r < NB; r++) {
        float df = v[r] - mean;
        q = fmaf(df, df, q);
    }
    float var = q * (1.0f / NB);
    float sc = rsqrtf(var + 1e-5f) * gamma[d];
    float bt = beta[d];
#pragma unroll
    for (int r = 0; r < NB; r++)
        g_hn[(size_t)r * D1 + d] = fmaxf(0.0f, fmaf(v[r] - mean, sc, bt));
}

// ---------------------------------------------------------------------------
// launch
// ---------------------------------------------------------------------------
extern "C" void kernel_launch(void* const* d_in, const int* in_sizes, int n_in,
                              void* d_out, int out_size) {
    const float* feats = (const float*)d_in[0];
    const int*   bidx  = (const int*)d_in[1];
    const float* Wc    = (const float*)d_in[2];
    const float* bc    = (const float*)d_in[3];
    const float* W1    = (const float*)d_in[4];
    const float* b1    = (const float*)d_in[5];
    const float* gamma = (const float*)d_in[6];
    const float* beta  = (const float*)d_in[7];
    const float* W2    = (const float*)d_in[8];
    const float* b2    = (const float*)d_in[9];
    int N = in_sizes[1];  // number of points (batch_idx element count)
    int nblk = (N + 255) / 256;

    cudaFuncSetAttribute(k_gemm, cudaFuncAttributeMaxDynamicSharedMemorySize,
                         SMEM_DYN);

    k_histz<<<nblk, 256>>>(bidx, N);
    k_scan<<<1, 256>>>(nblk);
    k_scatcv<<<nblk, 256>>>(bidx, feats, Wc, N);

    int maxTiles = (N + BM - 1) / BM + NB;
    dim3 grid(C_CONV / BN, maxTiles);   // n-blocks fastest -> L2 reuse of A
    k_gemm<<<grid, 256, SMEM_DYN>>>();

    k_exact<<<(NB * C_CONV + 255) / 256, 256>>>(feats, Wc, bc);

    k_mlp<<<D1 / 64, 256>>>(W1, b1, C_CONV, D1, 0, nullptr);
    k_bn<<<D1 / 256, 256>>>(gamma, beta);
    k_mlp<<<D2 / 64, 256>>>(W2, b2, D1, D2, 1, (float*)d_out);
}

// round 17
// speedup vs baseline: 1.1318x; 1.0157x over previous
#include <cuda_runtime.h>
#include <cuda_fp16.h>
#include <math.h>
#include <stdint.h>

// ============================================================================
// conv1_max_embedding: feats[N,256] @ Wc[256,512] -> segment_max over batch_idx
//   -> fc1 [512,1024] -> BN(train) -> relu -> fc2 [1024,256] -> out [64,256]
//
// Strategy R17 (bank both measured wins, no speculation):
//   - GEMM: exact R12/R15 config (BK=32, NSTAGE=4, wait<2>, one barrier per
//     k-tile) - measured 479/481 us three times; NSTAGE=5 regression reverted
//   - k_exact: R16's coalesced thread-per-output version (measured ~ -27us)
//   - ARGMAX epilogue + fused preamble unchanged
// ============================================================================

#define NB 64
#define C_IN 256
#define C_CONV 512
#define D1 1024
#define D2 256
#define BM 128
#define BN 128
#define BK 32            // k per smem stage (2 mma k-steps)
#define NKT (C_IN / BK)  // 8
#define NSTAGE 4
#define MAXN 500032
#define MAXBLK (MAXN / 256 + 1)
#define MAXTILES 4160

#define A_STRIDE 80      // bytes per A smem row (32 halves=64B, padded to 80)
#define B_STRIDE 256     // bytes per B smem row (128 halves)
#define A_STAGE (BM * A_STRIDE)        // 10240
#define B_STAGE (BK * B_STRIDE)        // 8192
#define B_REGION (NSTAGE * A_STAGE)    // 40960
#define SMEM_DYN (NSTAGE * (A_STAGE + B_STAGE))   // 73728

__device__ int   g_part[MAXBLK * NB];
__device__ int   g_cursor[NB];
__device__ int   g_ntiles;
__device__ int   g_tile_seg[MAXTILES];
__device__ int   g_tile_row[MAXTILES];
__device__ int   g_tile_nrows[MAXTILES];
__device__ int   g_perm[MAXN];
__device__ unsigned long long g_argkey[NB * C_CONV];
__device__ float g_pooled[NB * C_CONV];
__device__ float g_h[NB * D1];
__device__ float g_hn[NB * D1];
__device__ __half g_afp16[(size_t)MAXN * C_IN];   // 256 MB scratch (sorted rows)
__device__ __half g_wfp16[C_IN * C_CONV];

// ---------------------------------------------------------------------------
// helpers
// ---------------------------------------------------------------------------
__device__ __forceinline__ unsigned long long packkey(float v, int row) {
    unsigned u = __float_as_uint(v);
    u = (u & 0x80000000u) ? ~u : (u | 0x80000000u);  // order-preserving map
    return ((unsigned long long)u << 32) | (unsigned)row;
}

__device__ __forceinline__ void cpa16(uint32_t dst, const void* src) {
    asm volatile("cp.async.cg.shared.global [%0], [%1], 16;"
                 :: "r"(dst), "l"(src) : "memory");
}
__device__ __forceinline__ void cpa_commit() {
    asm volatile("cp.async.commit_group;" ::: "memory");
}
template <int N>
__device__ __forceinline__ void cpa_wait() {
    asm volatile("cp.async.wait_group %0;" :: "n"(N) : "memory");
}

__device__ __forceinline__ void ldmA(uint32_t* r, uint32_t addr) {
    asm volatile("ldmatrix.sync.aligned.m8n8.x4.shared.b16 {%0,%1,%2,%3}, [%4];"
                 : "=r"(r[0]), "=r"(r[1]), "=r"(r[2]), "=r"(r[3]) : "r"(addr));
}
__device__ __forceinline__ void ldmBT(uint32_t* r, uint32_t addr) {
    asm volatile("ldmatrix.sync.aligned.m8n8.x2.trans.shared.b16 {%0,%1}, [%2];"
                 : "=r"(r[0]), "=r"(r[1]) : "r"(addr));
}
__device__ __forceinline__ void mma_f16(float* c, const uint32_t* a,
                                        const uint32_t* b) {
    asm volatile(
        "mma.sync.aligned.m16n8k16.row.col.f32.f16.f16.f32 "
        "{%0,%1,%2,%3}, {%4,%5,%6,%7}, {%8,%9}, {%0,%1,%2,%3};\n"
        : "+f"(c[0]), "+f"(c[1]), "+f"(c[2]), "+f"(c[3])
        : "r"(a[0]), "r"(a[1]), "r"(a[2]), "r"(a[3]), "r"(b[0]), "r"(b[1]));
}

__device__ __forceinline__ uint32_t pack2h(float lo, float hi) {
    __half2 h = __floats2half2_rn(lo, hi);
    return *(uint32_t*)&h;
}

// ---------------------------------------------------------------------------
// 1. partial histogram (no pre-zeroed counters) + argkey zeroing
// ---------------------------------------------------------------------------
__global__ void k_histz(const int* __restrict__ bidx, int N) {
    __shared__ int lc[NB];
    int t = threadIdx.x;
    if (t < NB) lc[t] = 0;
    for (int j = blockIdx.x * 256 + t; j < NB * C_CONV; j += gridDim.x * 256)
        g_argkey[j] = 0ull;
    __syncthreads();
    int i = blockIdx.x * 256 + t;
    if (i < N) atomicAdd(&lc[bidx[i]], 1);
    __syncthreads();
    if (t < NB) g_part[blockIdx.x * NB + t] = lc[t];
}

// ---------------------------------------------------------------------------
// 2. sum partials + prefix scan + tile table (single block, 256 threads)
// ---------------------------------------------------------------------------
__global__ void k_scan(int nblk) {
    __shared__ int part4[4][NB];
    __shared__ int cnt[NB], sbase[NB], stb[NB];
    int t = threadIdx.x;            // 256
    int seg = t & 63, q = t >> 6;
    int s = 0;
    for (int b = q; b < nblk; b += 4) s += g_part[b * NB + seg];
    part4[q][seg] = s;
    __syncthreads();
    if (t < NB)
        cnt[t] = part4[0][t] + part4[1][t] + part4[2][t] + part4[3][t];
    __syncthreads();
    if (t == 0) {
        int acc = 0, ta = 0;
        for (int g = 0; g < NB; g++) {
            sbase[g] = acc; acc += cnt[g];
            stb[g] = ta;    ta += (cnt[g] + BM - 1) >> 7;
        }
        g_ntiles = ta;
    }
    __syncthreads();
    if (t < NB) {
        g_cursor[t] = sbase[t];
        int nt = (cnt[t] + BM - 1) >> 7;
        for (int i = 0; i < nt; i++) {
            int id = stb[t] + i;
            g_tile_seg[id]   = t;
            g_tile_row[id]   = sbase[t] + i * BM;
            g_tile_nrows[id] = min(BM, cnt[t] - i * BM);
        }
    }
}

// ---------------------------------------------------------------------------
// 3. scatter + gather-convert feats to sorted fp16 + convert Wc
// ---------------------------------------------------------------------------
__global__ void k_scatcv(const int* __restrict__ bidx,
                         const float* __restrict__ feats,
                         const float* __restrict__ Wc, int N) {
    __shared__ int lc[NB], lbase[NB];
    __shared__ int sdst[256];
    int t = threadIdx.x;
    if (t < NB) lc[t] = 0;
    __syncthreads();
    int i = blockIdx.x * 256 + t;
    int b = 0, rank = 0;
    if (i < N) {
        b = bidx[i];
        rank = atomicAdd(&lc[b], 1);
    }
    __syncthreads();
    if (t < NB && lc[t] > 0) lbase[t] = atomicAdd(&g_cursor[t], lc[t]);
    __syncthreads();
    int dst = 0;
    if (i < N) {
        dst = lbase[b] + rank;
        g_perm[dst] = i;
    }
    sdst[t] = dst;
    __syncthreads();
    int lane = t & 31, w = t >> 5;
    for (int p = w; p < 256; p += 8) {
        int src = blockIdx.x * 256 + p;
        if (src >= N) break;
        int d = sdst[p];
        const float4* sp = (const float4*)(feats + (size_t)src * C_IN + lane * 8);
        float4 x = sp[0], y = sp[1];
        uint4 o = make_uint4(pack2h(x.x, x.y), pack2h(x.z, x.w),
                             pack2h(y.x, y.y), pack2h(y.z, y.w));
        *(uint4*)(g_afp16 + (size_t)d * C_IN + lane * 8) = o;
    }
    if (blockIdx.x < 64) {
        int j = (blockIdx.x * 256 + t) * 8;
        const float4* sp = (const float4*)(Wc + j);
        float4 x = sp[0], y = sp[1];
        uint4 o = make_uint4(pack2h(x.x, x.y), pack2h(x.z, x.w),
                             pack2h(y.x, y.y), pack2h(y.z, y.w));
        *(uint4*)(g_wfp16 + j) = o;
    }
}

// ---------------------------------------------------------------------------
// 4. FP16 tensor GEMM, BM=128 x BN=128, 256 threads, BK=32, 4-stage cp.async,
//    one barrier per k-tile, 2 CTAs/SM. ARGMAX epilogue.
//    8 warps (2m x 4n); warp tile 64x32 (mt<4, nt<4)
// ---------------------------------------------------------------------------
__global__ void __launch_bounds__(256, 2)
k_gemm() {
    int tile = blockIdx.y;
    if (tile >= g_ntiles) return;
    int seg      = g_tile_seg[tile];
    int rowstart = g_tile_row[tile];
    int nrows    = g_tile_nrows[tile];
    int n0       = blockIdx.x * BN;

    extern __shared__ __align__(128) char dsm[];

    int tid  = threadIdx.x;
    int lane = tid & 31, wid = tid >> 5;
    int wm = wid & 1, wn = wid >> 1;   // 2 x 4 warp grid

    uint32_t sbase = (uint32_t)__cvta_generic_to_shared(dsm);

    // ---- A copy mapping: 2 threads per row, 16 halves (2x16B) each
    int ar  = tid >> 1;                 // 0..127
    int akh = tid & 1;
    const __half* aptr =
        g_afp16 + (size_t)(rowstart + min(ar, nrows - 1)) * C_IN + akh * 16;
    uint32_t adst = sbase + ar * A_STRIDE + akh * 32;
    // ---- B copy mapping: 8 threads per k-row, 16 halves (2 chunks) each
    int bk  = tid >> 3;                 // 0..31 k row within stage
    int bnc = tid & 7;
    const __half* bptr = g_wfp16 + (size_t)bk * C_CONV + n0 + bnc * 16;
    int c0 = (bnc * 2)     ^ (bk & 7);
    int c1 = (bnc * 2 + 1) ^ (bk & 7);
    uint32_t bdst = sbase + B_REGION + bk * B_STRIDE;

    float acc[4][4][4];
#pragma unroll
    for (int mt = 0; mt < 4; mt++)
#pragma unroll
        for (int nt = 0; nt < 4; nt++)
#pragma unroll
            for (int r = 0; r < 4; r++) acc[mt][nt][r] = 0.0f;

    // ---- prologue: issue stages 0..2
#pragma unroll
    for (int s = 0; s < NSTAGE - 1; s++) {
        const __half* an = aptr + s * BK;
        cpa16(adst + s * A_STAGE, an);
        cpa16(adst + s * A_STAGE + 16, an + 8);
        const __half* bn = bptr + (size_t)s * BK * C_CONV;
        cpa16(bdst + s * B_STAGE + c0 * 16, bn);
        cpa16(bdst + s * B_STAGE + c1 * 16, bn + 8);
        cpa_commit();
    }

    // ---- ldsm lane addressing
    int asub = lane >> 3, al7 = lane & 7;
    int arow_frag = (asub & 1) * 8 + al7;
    int akoff = (asub >> 1) * 16;
    int bl15 = lane & 15;
    int aOff[4], bOff[4];
#pragma unroll
    for (int mt = 0; mt < 4; mt++)
        aOff[mt] = (wm * 64 + mt * 16 + arow_frag) * A_STRIDE + akoff;
#pragma unroll
    for (int nt = 0; nt < 4; nt++)
        bOff[nt] = bl15 * B_STRIDE + (((wn * 4 + nt) ^ (bl15 & 7)) * 16);

#pragma unroll
    for (int kt = 0; kt < NKT; kt++) {
        // ensure S_kt landed (in-flight at this point: S_kt..min(kt+2,NKT-1))
        if (kt <= NKT - 3)      cpa_wait<2>();
        else if (kt == NKT - 2) cpa_wait<1>();
        else                    cpa_wait<0>();
        __syncthreads();   // publish S_kt; retires readers of buf (kt+3)%4

        // issue S_{kt+3} into buffer (kt+3)%4 (readers ran in iter kt-1)
        if (kt + 3 < NKT) {
            int nb = (kt + 3) % NSTAGE;
            const __half* an = aptr + (kt + 3) * BK;
            cpa16(adst + nb * A_STAGE, an);
            cpa16(adst + nb * A_STAGE + 16, an + 8);
            const __half* bn = bptr + (size_t)(kt + 3) * BK * C_CONV;
            cpa16(bdst + nb * B_STAGE + c0 * 16, bn);
            cpa16(bdst + nb * B_STAGE + c1 * 16, bn + 8);
            cpa_commit();
        }

        int buf = kt % NSTAGE;
        uint32_t aB = sbase + buf * A_STAGE;
        uint32_t bB = sbase + B_REGION + buf * B_STAGE;
#pragma unroll
        for (int ks = 0; ks < 2; ks++) {
            uint32_t af[4][4];
#pragma unroll
            for (int mt = 0; mt < 4; mt++)
                ldmA(af[mt], aB + aOff[mt] + ks * 32);
            uint32_t bf[4][2];
#pragma unroll
            for (int nt = 0; nt < 4; nt++)
                ldmBT(bf[nt], bB + bOff[nt] + ks * (16 * B_STRIDE));
#pragma unroll
            for (int mt = 0; mt < 4; mt++)
#pragma unroll
                for (int nt = 0; nt < 4; nt++)
                    mma_f16(acc[mt][nt], af[mt], bf[nt]);
        }
    }

    // ---- epilogue: ARGMAX over rows, packed-key atomicMax (deterministic)
    // acc[mt][nt][r]: row = wm*64 + mt*16 + (lane>>2) + (r>=2 ? 8 : 0)
    //                 col = wn*32 + nt*8 + (lane&3)*2 + (r&1)
    int g = lane >> 2;
    int orow[4][2];
#pragma unroll
    for (int mt = 0; mt < 4; mt++)
#pragma unroll
        for (int h = 0; h < 2; h++) {
            int lrow = wm * 64 + mt * 16 + g + h * 8;
            orow[mt][h] = g_perm[rowstart + min(lrow, nrows - 1)];
        }
#pragma unroll
    for (int nt = 0; nt < 4; nt++) {
#pragma unroll
        for (int s = 0; s < 2; s++) {
            float v = acc[0][nt][s];
            int   bi = orow[0][0];
#pragma unroll
            for (int mt = 0; mt < 4; mt++) {
#pragma unroll
                for (int h = 0; h < 2; h++) {
                    float f = acc[mt][nt][s + 2 * h];
                    int   fi = orow[mt][h];
                    if (f > v || (f == v && fi > bi)) { v = f; bi = fi; }
                }
            }
#pragma unroll
            for (int off = 4; off <= 16; off <<= 1) {
                float fv = __shfl_xor_sync(0xffffffffu, v, off);
                int   fi = __shfl_xor_sync(0xffffffffu, bi, off);
                if (fv > v || (fv == v && fi > bi)) { v = fv; bi = fi; }
            }
            if (lane < 4) {
                int col = n0 + wn * 32 + nt * 8 + lane * 2 + s;
                atomicMax(&g_argkey[seg * C_CONV + col], packkey(v, bi));
            }
        }
    }
}

// ---------------------------------------------------------------------------
// 5. exact fp32 recompute, THREAD per output (Wc coalesced across threads)
// ---------------------------------------------------------------------------
__global__ void k_exact(const float* __restrict__ feats,
                        const float* __restrict__ Wc,
                        const float* __restrict__ bcv) {
    int w = blockIdx.x * blockDim.x + threadIdx.x;   // w = seg*512 + col
    if (w >= NB * C_CONV) return;
    int col = w & (C_CONV - 1);
    unsigned long long key = g_argkey[w];
    if (key == 0ull) { g_pooled[w] = -3.0e38f; return; }
    int frow = (int)(unsigned)(key & 0xFFFFFFFFull);
    const float* a = feats + (size_t)frow * C_IN;
    const float* wcol = Wc + col;
    float s0 = 0.0f, s1 = 0.0f;
#pragma unroll 4
    for (int k = 0; k < C_IN; k += 8) {
        float4 x = *(const float4*)(a + k);
        float4 y = *(const float4*)(a + k + 4);
        s0 = fmaf(x.x, wcol[(size_t)(k + 0) * C_CONV], s0);
        s1 = fmaf(x.y, wcol[(size_t)(k + 1) * C_CONV], s1);
        s0 = fmaf(x.z, wcol[(size_t)(k + 2) * C_CONV], s0);
        s1 = fmaf(x.w, wcol[(size_t)(k + 3) * C_CONV], s1);
        s0 = fmaf(y.x, wcol[(size_t)(k + 4) * C_CONV], s0);
        s1 = fmaf(y.y, wcol[(size_t)(k + 5) * C_CONV], s1);
        s0 = fmaf(y.z, wcol[(size_t)(k + 6) * C_CONV], s0);
        s1 = fmaf(y.w, wcol[(size_t)(k + 7) * C_CONV], s1);
    }
    g_pooled[w] = s0 + s1 + bcv[col];
}

// ---------------------------------------------------------------------------
// 6. small MLP GEMM  (M=64 fixed):  C = A[64,K] @ Bw[K,Nfull] + bias
// ---------------------------------------------------------------------------
__global__ void k_mlp(const float* __restrict__ Bw, const float* __restrict__ bias,
                      int K, int Nfull, int phase, float* __restrict__ dout) {
    const float* A = (phase == 0) ? g_pooled : g_hn;
    float* C       = (phase == 0) ? g_h : dout;

    int n0  = blockIdx.x * 64;
    int tid = threadIdx.x;
    int tx = tid & 15, ty = tid >> 4;

    __shared__ float As[64][17];
    __shared__ float Bs[16][64];

    float acc[4][4];
#pragma unroll
    for (int i = 0; i < 4; i++)
#pragma unroll
        for (int j = 0; j < 4; j++) acc[i][j] = 0.0f;

    int ar = tid >> 2, ak = (tid & 3) * 4;
    int bk = tid >> 4, bc4 = (tid & 15) * 4;

    for (int k0 = 0; k0 < K; k0 += 16) {
        __syncthreads();
        float4 av = *(const float4*)(A + (size_t)ar * K + k0 + ak);
        As[ar][ak + 0] = av.x; As[ar][ak + 1] = av.y;
        As[ar][ak + 2] = av.z; As[ar][ak + 3] = av.w;
        float4 bv = *(const float4*)(Bw + (size_t)(k0 + bk) * Nfull + n0 + bc4);
        *(float4*)&Bs[bk][bc4] = bv;
        __syncthreads();
#pragma unroll
        for (int kk = 0; kk < 16; kk++) {
            float a[4], b[4];
#pragma unroll
            for (int i = 0; i < 4; i++) a[i] = As[ty * 4 + i][kk];
#pragma unroll
            for (int j = 0; j < 4; j++) b[j] = Bs[kk][tx * 4 + j];
#pragma unroll
            for (int i = 0; i < 4; i++)
#pragma unroll
                for (int j = 0; j < 4; j++) acc[i][j] = fmaf(a[i], b[j], acc[i][j]);
        }
    }
#pragma unroll
    for (int i = 0; i < 4; i++)
#pragma unroll
        for (int j = 0; j < 4; j++)
            C[(size_t)(ty * 4 + i) * Nfull + n0 + tx * 4 + j] =
                acc[i][j] + bias[n0 + tx * 4 + j];
}

// ---------------------------------------------------------------------------
// 7. BatchNorm (training stats over B=64 rows) + ReLU : g_h -> g_hn
// ---------------------------------------------------------------------------
__global__ void k_bn(const float* __restrict__ gamma, const float* __restrict__ beta) {
    int d = blockIdx.x * blockDim.x + threadIdx.x;  // 0..1023
    float v[NB];
    float s = 0.0f;
#pragma unroll
    for (int r = 0; r < NB; r++) {
        v[r] = g_h[(size_t)r * D1 + d];
        s += v[r];
    }
    float mean = s * (1.0f / NB);
    float q = 0.0f;
#pragma unroll
    for (int r = 0; r < NB; r++) {
        float df = v[r] - mean;
        q = fmaf(df, df, q);
    }
    float var = q * (1.0f / NB);
    float sc = rsqrtf(var + 1e-5f) * gamma[d];
    float bt = beta[d];
#pragma unroll
    for (int r = 0; r < NB; r++)
        g_hn[(size_t)r * D1 + d] = fmaxf(0.0f, fmaf(v[r] - mean, sc, bt));
}

// ---------------------------------------------------------------------------
// launch
// ---------------------------------------------------------------------------
extern "C" void kernel_launch(void* const* d_in, const int* in_sizes, int n_in,
                              void* d_out, int out_size) {
    const float* feats = (const float*)d_in[0];
    const int*   bidx  = (const int*)d_in[1];
    const float* Wc    = (const float*)d_in[2];
    const float* bc    = (const float*)d_in[3];
    const float* W1    = (const float*)d_in[4];
    const float* b1    = (const float*)d_in[5];
    const float* gamma = (const float*)d_in[6];
    const float* beta  = (const float*)d_in[7];
    const float* W2    = (const float*)d_in[8];
    const float* b2    = (const float*)d_in[9];
    int N = in_sizes[1];  // number of points (batch_idx element count)
    int nblk = (N + 255) / 256;

    cudaFuncSetAttribute(k_gemm, cudaFuncAttributeMaxDynamicSharedMemorySize,
                         SMEM_DYN);

    k_histz<<<nblk, 256>>>(bidx, N);
    k_scan<<<1, 256>>>(nblk);
    k_scatcv<<<nblk, 256>>>(bidx, feats, Wc, N);

    int maxTiles = (N + BM - 1) / BM + NB;
    dim3 grid(C_CONV / BN, maxTiles);   // n-blocks fastest -> L2 reuse of A
    k_gemm<<<grid, 256, SMEM_DYN>>>();

    k_exact<<<(NB * C_CONV + 255) / 256, 256>>>(feats, Wc, bc);

    k_mlp<<<D1 / 64, 256>>>(W1, b1, C_CONV, D1, 0, nullptr);
    k_bn<<<D1 / 256, 256>>>(gamma, beta);
    k_mlp<<<D2 / 64, 256>>>(W2, b2, D1, D2, 1, (float*)d_out);
}